// round 11
// baseline (speedup 1.0000x reference)
#include <cuda_runtime.h>
#include <math.h>
#include <stdint.h>

#define N_TOT 8192
#define F_DIM 128
#define TBLK  64                 // 8192 / 128
#define NTILES (TBLK*(TBLK+1)/2) // 2080 upper-triangle tiles
#define TILEB 16384              // 128 rows x 128B (int8), XOR-swizzled
#define SM_TOTAL (2 * TILEB)     // A + B = 32KB

// Device scratch (allocation-free rules)
__device__ uint8_t g_x8[N_TOT * F_DIM];   // normalized feats [N][F], s8 = round(x*127)
__device__ float g_part[NTILES];

__device__ __forceinline__ uint32_t smem_u32(const void* p) {
    uint32_t a;
    asm("{ .reg .u64 t; cvta.to.shared.u64 t, %1; cvt.u32.u64 %0, t; }" : "=r"(a) : "l"(p));
    return a;
}
__device__ __forceinline__ float ex2a(float x) {
    float y; asm("ex2.approx.f32 %0, %1;" : "=f"(y) : "f"(x)); return y;
}
#define CPA16(dst, src) \
    asm volatile("cp.async.cg.shared.global [%0], [%1], 16;" :: "r"(dst), "l"(src))

// ---------------------------------------------------------------------------
// Kernel 1: normalize + int8 quantize (scale 127). 16 rows per block.
// ---------------------------------------------------------------------------
__global__ void __launch_bounds__(256) normalize_kernel(const float* __restrict__ x) {
    __shared__ float sm[16 * 130];
    __shared__ float ssp[16][17];
    __shared__ float rn[16];

    const int tid = threadIdx.x;
    const int n0  = blockIdx.x * 16;
    const int b   = n0 >> 10;
    const int thw0 = n0 & 1023;
    const float* base = x + (size_t)b * 131072 + thw0;

#pragma unroll
    for (int it = 0; it < 2; ++it) {
        int idx = it * 256 + tid;
        int q = idx & 3;
        int f = idx >> 2;
        float4 v = *(const float4*)&base[(size_t)f * 1024 + q * 4];
        sm[(q * 4 + 0) * 130 + f] = v.x;
        sm[(q * 4 + 1) * 130 + f] = v.y;
        sm[(q * 4 + 2) * 130 + f] = v.z;
        sm[(q * 4 + 3) * 130 + f] = v.w;
    }
    __syncthreads();
    {
        int r = tid & 15, part = tid >> 4;
        float ss = 0.f;
#pragma unroll
        for (int f = part * 8; f < part * 8 + 8; ++f) {
            float v = sm[r * 130 + f];
            ss += v * v;
        }
        ssp[part][r] = ss;
    }
    __syncthreads();
    if (tid < 16) {
        float ss = 0.f;
#pragma unroll
        for (int p = 0; p < 16; ++p) ss += ssp[p][tid];
        rn[tid] = 127.0f / fmaxf(sqrtf(ss), 1e-12f);   // normalize + quant scale
    }
    __syncthreads();
    uint32_t* out = (uint32_t*)(g_x8 + (size_t)n0 * F_DIM);
#pragma unroll
    for (int it = 0; it < 2; ++it) {
        int idx = it * 256 + tid;     // 512 u32 words total (16 rows x 32)
        int f4 = idx & 31;
        int r  = idx >> 5;
        float s = rn[r];
        const float* p = &sm[r * 130 + f4 * 4];
        int i0 = __float2int_rn(p[0] * s);
        int i1 = __float2int_rn(p[1] * s);
        int i2 = __float2int_rn(p[2] * s);
        int i3 = __float2int_rn(p[3] * s);
        out[r * 32 + f4] = (uint32_t)(i0 & 0xFF) | ((uint32_t)(i1 & 0xFF) << 8) |
                           ((uint32_t)(i2 & 0xFF) << 16) | ((uint32_t)(i3 & 0xFF) << 24);
    }
}

// ---------------------------------------------------------------------------
// Kernel 2: INT8 IMMA (m16n8k32) 128x128x128 tile + fused exp2-sum.
// 16 warps, 32x32 warp tiles. Same layout/addressing as the verified fp8 k32.
// ---------------------------------------------------------------------------
__global__ void __launch_bounds__(512, 2) simexp_kernel() {
    extern __shared__ char smem[];
    const uint32_t sbase = smem_u32(smem);
    const int tid  = threadIdx.x;
    const int wid  = tid >> 5;
    const int lane = tid & 31;

    // linear tile id -> (bi, bj), bj >= bi
    int t = blockIdx.x;
    int bi = (int)((129.0f - sqrtf(16641.0f - 8.0f * (float)t)) * 0.5f);
    while ((bi + 1) * (129 - (bi + 1)) / 2 <= t) ++bi;
    while (bi * (129 - bi) / 2 > t) --bi;
    const int bj = bi + (t - bi * (129 - bi) / 2);
    const bool diag = (bi == bj);

    // cooperative tile loads (1024 x 16B chunks over 512 threads)
    {
        const char* gA = (const char*)(g_x8 + (size_t)bi * 128 * F_DIM);
#pragma unroll
        for (int it = 0; it < 2; ++it) {
            int idx = it * 512 + tid;
            int r = idx >> 3, q = idx & 7;
            CPA16(sbase + r * 128 + ((q ^ (r & 7)) << 4), gA + (size_t)idx * 16);
        }
        if (!diag) {
            const char* gB = (const char*)(g_x8 + (size_t)bj * 128 * F_DIM);
#pragma unroll
            for (int it = 0; it < 2; ++it) {
                int idx = it * 512 + tid;
                int r = idx >> 3, q = idx & 7;
                CPA16(sbase + TILEB + r * 128 + ((q ^ (r & 7)) << 4), gB + (size_t)idx * 16);
            }
        }
        asm volatile("cp.async.commit_group;");
        asm volatile("cp.async.wait_group 0;" ::: "memory");
    }
    __syncthreads();

    const uint32_t aBase = sbase;
    const uint32_t bBase = diag ? sbase : (sbase + TILEB);

    const int wm = (wid >> 2) * 32;   // 4x4 warp grid
    const int wn = (wid & 3) * 32;
    const int g  = lane >> 3;
    const int lr = lane & 7;
    const int lrow = lane >> 2;
    const int lcol = (lane & 3) * 2;

    int acc[2][4][4];
#pragma unroll
    for (int mt = 0; mt < 2; ++mt)
#pragma unroll
        for (int nt = 0; nt < 4; ++nt)
#pragma unroll
            for (int c = 0; c < 4; ++c) acc[mt][nt][c] = 0;

#pragma unroll
    for (int kc = 0; kc < 4; ++kc) {      // K=128 in chunks of 32 (int8)
        const int qa = kc * 2 + (g >> 1);
        const int qb = kc * 2 + (g & 1);
        uint32_t a[2][4];
#pragma unroll
        for (int mt = 0; mt < 2; ++mt) {
            int row = wm + mt * 16 + (g & 1) * 8 + lr;   // row & 7 == lr
            uint32_t addr = aBase + row * 128 + ((qa ^ lr) << 4);
            asm volatile("ldmatrix.sync.aligned.m8n8.x4.shared.b16 {%0,%1,%2,%3}, [%4];"
                         : "=r"(a[mt][0]), "=r"(a[mt][1]), "=r"(a[mt][2]), "=r"(a[mt][3])
                         : "r"(addr));
        }
        uint32_t bf[2][4];
#pragma unroll
        for (int np = 0; np < 2; ++np) {
            int row = wn + np * 16 + (g >> 1) * 8 + lr;  // row & 7 == lr
            uint32_t addr = bBase + row * 128 + ((qb ^ lr) << 4);
            asm volatile("ldmatrix.sync.aligned.m8n8.x4.shared.b16 {%0,%1,%2,%3}, [%4];"
                         : "=r"(bf[np][0]), "=r"(bf[np][1]), "=r"(bf[np][2]), "=r"(bf[np][3])
                         : "r"(addr));
        }
#pragma unroll
        for (int mt = 0; mt < 2; ++mt)
#pragma unroll
            for (int nt = 0; nt < 4; ++nt) {
                uint32_t b0 = bf[nt >> 1][(nt & 1) * 2];
                uint32_t b1 = bf[nt >> 1][(nt & 1) * 2 + 1];
                asm volatile(
                    "mma.sync.aligned.m16n8k32.row.col.s32.s8.s8.s32 "
                    "{%0,%1,%2,%3}, {%4,%5,%6,%7}, {%8,%9}, {%0,%1,%2,%3};"
                    : "+r"(acc[mt][nt][0]), "+r"(acc[mt][nt][1]),
                      "+r"(acc[mt][nt][2]), "+r"(acc[mt][nt][3])
                    : "r"(a[mt][0]), "r"(a[mt][1]), "r"(a[mt][2]), "r"(a[mt][3]),
                      "r"(b0), "r"(b1));
            }
    }

    // epilogue: 2^(acc * SC); SC = (10/ln2) / 127^2. Skip i==j on diag tiles.
    const float SC = 14.4269504088896f / 16129.0f;
    float s = 0.f;
#pragma unroll
    for (int mt = 0; mt < 2; ++mt)
#pragma unroll
        for (int nt = 0; nt < 4; ++nt)
#pragma unroll
            for (int c = 0; c < 4; ++c) {
                int r_ = wm + mt * 16 + ((c >> 1) << 3) + lrow;
                int c_ = wn + nt * 8 + lcol + (c & 1);
                if (diag && r_ == c_) continue;
                s += ex2a((float)acc[mt][nt][c] * SC);
            }
    if (!diag) s *= 2.f;

    __shared__ float red[16];
#pragma unroll
    for (int off = 16; off > 0; off >>= 1)
        s += __shfl_down_sync(0xFFFFFFFFu, s, off);
    if (lane == 0) red[wid] = s;
    __syncthreads();
    if (tid == 0) {
        float tsum = 0.f;
#pragma unroll
        for (int w = 0; w < 16; ++w) tsum += red[w];
        g_part[blockIdx.x] = tsum;
    }
}

// ---------------------------------------------------------------------------
// Kernel 3: deterministic final reduction + log
// ---------------------------------------------------------------------------
__global__ void __launch_bounds__(256) finalize_kernel(float* __restrict__ out) {
    __shared__ float red[8];
    float s = 0.f;
    for (int i = threadIdx.x; i < NTILES; i += 256) s += g_part[i];
#pragma unroll
    for (int off = 16; off > 0; off >>= 1)
        s += __shfl_down_sync(0xFFFFFFFFu, s, off);
    if ((threadIdx.x & 31) == 0) red[threadIdx.x >> 5] = s;
    __syncthreads();
    if (threadIdx.x == 0) {
        float tsum = 0.f;
#pragma unroll
        for (int w = 0; w < 8; ++w) tsum += red[w];
        out[0] = logf(tsum);
    }
}

extern "C" void kernel_launch(void* const* d_in, const int* in_sizes, int n_in,
                              void* d_out, int out_size) {
    const float* x = (const float*)d_in[0];
    float* out = (float*)d_out;
    (void)in_sizes; (void)n_in; (void)out_size;

    cudaFuncSetAttribute(simexp_kernel, cudaFuncAttributeMaxDynamicSharedMemorySize, SM_TOTAL);

    normalize_kernel<<<N_TOT / 16, 256>>>(x);
    simexp_kernel<<<NTILES, 512, SM_TOTAL>>>();
    finalize_kernel<<<1, 256>>>(out);
}

// round 12
// speedup vs baseline: 1.7655x; 1.7655x over previous
#include <cuda_runtime.h>
#include <cuda_fp16.h>
#include <math.h>
#include <stdint.h>

#define N_TOT 8192
#define F_DIM 128
#define TBLK  64                 // 8192 / 128
#define NTILES (TBLK*(TBLK+1)/2) // 2080 upper-triangle tiles
#define TILEB 32768              // 128 rows x 256B (fp16), XOR-swizzled
#define SM_TOTAL (2 * TILEB)     // A + B = 64KB

// Device scratch (allocation-free rules)
__device__ __half g_xh[N_TOT * F_DIM];   // scaled normalized feats [N][F] fp16
__device__ float g_part[NTILES];

__device__ __forceinline__ uint32_t smem_u32(const void* p) {
    uint32_t a;
    asm("{ .reg .u64 t; cvta.to.shared.u64 t, %1; cvt.u32.u64 %0, t; }" : "=r"(a) : "l"(p));
    return a;
}
__device__ __forceinline__ float ex2a(float x) {
    float y; asm("ex2.approx.f32 %0, %1;" : "=f"(y) : "f"(x)); return y;
}
#define CPA16(dst, src) \
    asm volatile("cp.async.cg.shared.global [%0], [%1], 16;" :: "r"(dst), "l"(src))

// ---------------------------------------------------------------------------
// Kernel 1: normalize + fold sqrt(10/ln2) + fp16 convert. 16 rows per block.
// ---------------------------------------------------------------------------
__global__ void __launch_bounds__(256) normalize_kernel(const float* __restrict__ x) {
    __shared__ float sm[16 * 130];
    __shared__ float ssp[16][17];
    __shared__ float rn[16];

    const int tid = threadIdx.x;
    const int n0  = blockIdx.x * 16;
    const int b   = n0 >> 10;
    const int thw0 = n0 & 1023;
    const float* base = x + (size_t)b * 131072 + thw0;

#pragma unroll
    for (int it = 0; it < 2; ++it) {
        int idx = it * 256 + tid;
        int q = idx & 3;
        int f = idx >> 2;
        float4 v = *(const float4*)&base[(size_t)f * 1024 + q * 4];
        sm[(q * 4 + 0) * 130 + f] = v.x;
        sm[(q * 4 + 1) * 130 + f] = v.y;
        sm[(q * 4 + 2) * 130 + f] = v.z;
        sm[(q * 4 + 3) * 130 + f] = v.w;
    }
    __syncthreads();
    {
        int r = tid & 15, part = tid >> 4;
        float ss = 0.f;
#pragma unroll
        for (int f = part * 8; f < part * 8 + 8; ++f) {
            float v = sm[r * 130 + f];
            ss += v * v;
        }
        ssp[part][r] = ss;
    }
    __syncthreads();
    if (tid < 16) {
        float ss = 0.f;
#pragma unroll
        for (int p = 0; p < 16; ++p) ss += ssp[p][tid];
        // 3.7982825 = sqrt(10 / ln 2): folds the exp2 scale into the data
        rn[tid] = (1.0f / fmaxf(sqrtf(ss), 1e-12f)) * 3.7982825f;
    }
    __syncthreads();
    uint32_t* out = (uint32_t*)(g_xh + (size_t)n0 * F_DIM);
#pragma unroll
    for (int it = 0; it < 4; ++it) {
        int idx = it * 256 + tid;
        int f2 = idx & 63;
        int r  = idx >> 6;
        float s = rn[r];
        float2 v = *(const float2*)&sm[r * 130 + f2 * 2];
        __half2 h = __floats2half2_rn(v.x * s, v.y * s);
        out[r * 64 + f2] = *(uint32_t*)&h;
    }
}

// ---------------------------------------------------------------------------
// Kernel 2: HMMA fp16 (f16 accumulate) 128x128x128 tile + fused exp2-sum.
// 16 warps, 32x32 warp tiles, XOR-swizzled smem (verified layout).
// ---------------------------------------------------------------------------
__global__ void __launch_bounds__(512, 2) simexp_kernel() {
    extern __shared__ char smem[];
    const uint32_t sbase = smem_u32(smem);
    const int tid  = threadIdx.x;
    const int wid  = tid >> 5;
    const int lane = tid & 31;

    // linear tile id -> (bi, bj), bj >= bi
    int t = blockIdx.x;
    int bi = (int)((129.0f - sqrtf(16641.0f - 8.0f * (float)t)) * 0.5f);
    while ((bi + 1) * (129 - (bi + 1)) / 2 <= t) ++bi;
    while (bi * (129 - bi) / 2 > t) --bi;
    const int bj = bi + (t - bi * (129 - bi) / 2);
    const bool diag = (bi == bj);

    // cooperative tile loads (2048 x 16B chunks over 512 threads)
    {
        const char* gA = (const char*)(g_xh + (size_t)bi * 128 * F_DIM);
#pragma unroll
        for (int it = 0; it < 4; ++it) {
            int idx = it * 512 + tid;
            int r = idx >> 4, q = idx & 15;
            CPA16(sbase + r * 256 + ((q ^ (r & 7)) << 4), gA + (size_t)idx * 16);
        }
        if (!diag) {
            const char* gB = (const char*)(g_xh + (size_t)bj * 128 * F_DIM);
#pragma unroll
            for (int it = 0; it < 4; ++it) {
                int idx = it * 512 + tid;
                int r = idx >> 4, q = idx & 15;
                CPA16(sbase + TILEB + r * 256 + ((q ^ (r & 7)) << 4), gB + (size_t)idx * 16);
            }
        }
        asm volatile("cp.async.commit_group;");
        asm volatile("cp.async.wait_group 0;" ::: "memory");
    }
    __syncthreads();

    const uint32_t aBase = sbase;
    const uint32_t bBase = diag ? sbase : (sbase + TILEB);

    const int wm = (wid >> 2) * 32;   // 4x4 warp grid
    const int wn = (wid & 3) * 32;
    const int g  = lane >> 3;
    const int lr = lane & 7;
    const int lrow = lane >> 2;
    const int lcol = (lane & 3) * 2;

    uint32_t acc[2][4][2];            // f16x2 packed accumulators
#pragma unroll
    for (int mt = 0; mt < 2; ++mt)
#pragma unroll
        for (int nt = 0; nt < 4; ++nt) {
            acc[mt][nt][0] = 0u;
            acc[mt][nt][1] = 0u;
        }

#pragma unroll
    for (int kc = 0; kc < 8; ++kc) {
        const int qa = kc * 2 + (g >> 1);
        const int qb = kc * 2 + (g & 1);
        uint32_t a[2][4];
#pragma unroll
        for (int mt = 0; mt < 2; ++mt) {
            int row = wm + mt * 16 + (g & 1) * 8 + lr;   // row & 7 == lr
            uint32_t addr = aBase + row * 256 + ((qa ^ lr) << 4);
            asm volatile("ldmatrix.sync.aligned.m8n8.x4.shared.b16 {%0,%1,%2,%3}, [%4];"
                         : "=r"(a[mt][0]), "=r"(a[mt][1]), "=r"(a[mt][2]), "=r"(a[mt][3])
                         : "r"(addr));
        }
        uint32_t bf[2][4];
#pragma unroll
        for (int np = 0; np < 2; ++np) {
            int row = wn + np * 16 + (g >> 1) * 8 + lr;  // row & 7 == lr
            uint32_t addr = bBase + row * 256 + ((qb ^ lr) << 4);
            asm volatile("ldmatrix.sync.aligned.m8n8.x4.shared.b16 {%0,%1,%2,%3}, [%4];"
                         : "=r"(bf[np][0]), "=r"(bf[np][1]), "=r"(bf[np][2]), "=r"(bf[np][3])
                         : "r"(addr));
        }
#pragma unroll
        for (int mt = 0; mt < 2; ++mt)
#pragma unroll
            for (int nt = 0; nt < 4; ++nt) {
                uint32_t b0 = bf[nt >> 1][(nt & 1) * 2];
                uint32_t b1 = bf[nt >> 1][(nt & 1) * 2 + 1];
                asm volatile(
                    "mma.sync.aligned.m16n8k16.row.col.f16.f16.f16.f16 "
                    "{%0,%1}, {%2,%3,%4,%5}, {%6,%7}, {%0,%1};"
                    : "+r"(acc[mt][nt][0]), "+r"(acc[mt][nt][1])
                    : "r"(a[mt][0]), "r"(a[mt][1]), "r"(a[mt][2]), "r"(a[mt][3]),
                      "r"(b0), "r"(b1));
            }
    }

    // epilogue: scale pre-folded -> bare 2^acc; skip i==j on diag tiles
    float s = 0.f;
#pragma unroll
    for (int mt = 0; mt < 2; ++mt)
#pragma unroll
        for (int nt = 0; nt < 4; ++nt)
#pragma unroll
            for (int h = 0; h < 2; ++h) {       // h=0: row lrow, h=1: row lrow+8
                int r_ = wm + mt * 16 + h * 8 + lrow;
                int c0 = wn + nt * 8 + lcol;
                float2 f = __half22float2(*(__half2*)&acc[mt][nt][h]);
                if (!diag || r_ != c0)     s += ex2a(f.x);
                if (!diag || r_ != c0 + 1) s += ex2a(f.y);
            }
    if (!diag) s *= 2.f;

    __shared__ float red[16];
#pragma unroll
    for (int off = 16; off > 0; off >>= 1)
        s += __shfl_down_sync(0xFFFFFFFFu, s, off);
    if (lane == 0) red[wid] = s;
    __syncthreads();
    if (tid == 0) {
        float tsum = 0.f;
#pragma unroll
        for (int w = 0; w < 16; ++w) tsum += red[w];
        g_part[blockIdx.x] = tsum;
    }
}

// ---------------------------------------------------------------------------
// Kernel 3: deterministic final reduction + log
// ---------------------------------------------------------------------------
__global__ void __launch_bounds__(256) finalize_kernel(float* __restrict__ out) {
    __shared__ float red[8];
    float s = 0.f;
    for (int i = threadIdx.x; i < NTILES; i += 256) s += g_part[i];
#pragma unroll
    for (int off = 16; off > 0; off >>= 1)
        s += __shfl_down_sync(0xFFFFFFFFu, s, off);
    if ((threadIdx.x & 31) == 0) red[threadIdx.x >> 5] = s;
    __syncthreads();
    if (threadIdx.x == 0) {
        float tsum = 0.f;
#pragma unroll
        for (int w = 0; w < 8; ++w) tsum += red[w];
        out[0] = logf(tsum);
    }
}

extern "C" void kernel_launch(void* const* d_in, const int* in_sizes, int n_in,
                              void* d_out, int out_size) {
    const float* x = (const float*)d_in[0];
    float* out = (float*)d_out;
    (void)in_sizes; (void)n_in; (void)out_size;

    cudaFuncSetAttribute(simexp_kernel, cudaFuncAttributeMaxDynamicSharedMemorySize, SM_TOTAL);

    normalize_kernel<<<N_TOT / 16, 256>>>(x);
    simexp_kernel<<<NTILES, 512, SM_TOTAL>>>();
    finalize_kernel<<<1, 256>>>(out);
}

// round 13
// speedup vs baseline: 1.7784x; 1.0073x over previous
#include <cuda_runtime.h>
#include <cuda_fp16.h>
#include <math.h>
#include <stdint.h>

#define N_TOT 8192
#define F_DIM 128
#define TBLK  64                 // 8192 / 128
#define NTILES (TBLK*(TBLK+1)/2) // 2080 upper-triangle tiles
#define TILEB 32768              // 128 rows x 256B (fp16), XOR-swizzled
#define SM_TOTAL (2 * TILEB)     // A + B = 64KB

// Device scratch (allocation-free rules)
__device__ __half g_xh[N_TOT * F_DIM];   // scaled normalized feats [N][F] fp16
__device__ float g_part[NTILES];

__device__ __forceinline__ uint32_t smem_u32(const void* p) {
    uint32_t a;
    asm("{ .reg .u64 t; cvta.to.shared.u64 t, %1; cvt.u32.u64 %0, t; }" : "=r"(a) : "l"(p));
    return a;
}
__device__ __forceinline__ float ex2a(float x) {
    float y; asm("ex2.approx.f32 %0, %1;" : "=f"(y) : "f"(x)); return y;
}
#define CPA16(dst, src) \
    asm volatile("cp.async.cg.shared.global [%0], [%1], 16;" :: "r"(dst), "l"(src))

// ---------------------------------------------------------------------------
// Kernel 1: normalize + fold sqrt(10/ln2) + fp16 convert.
// 8 rows per block, 1 warp per row: single load round, one sync, shuffle norm.
// ---------------------------------------------------------------------------
__global__ void __launch_bounds__(256) normalize_kernel(const float* __restrict__ x) {
    __shared__ float sm[8 * 130];

    const int tid = threadIdx.x;
    const int n0  = blockIdx.x * 8;
    const int b   = n0 >> 10;
    const int thw0 = n0 & 1023;
    const float* base = x + (size_t)b * 131072 + thw0;

    // gather-transpose: thread = (f, q); 16 full 32B sectors per warp
    {
        int q = tid & 1;           // float4 index along n (8 n = 2 float4)
        int f = tid >> 1;          // 0..127
        float4 v = *(const float4*)&base[(size_t)f * 1024 + q * 4];
        sm[(q * 4 + 0) * 130 + f] = v.x;
        sm[(q * 4 + 1) * 130 + f] = v.y;
        sm[(q * 4 + 2) * 130 + f] = v.z;
        sm[(q * 4 + 3) * 130 + f] = v.w;
    }
    __syncthreads();

    // one warp per row: norm via shuffle, then write fp16x2 coalesced
    const int w    = tid >> 5;      // row in block
    const int lane = tid & 31;
    const float* row = &sm[w * 130];

    float a0 = row[2 * lane];
    float a1 = row[2 * lane + 1];
    float b0 = row[64 + 2 * lane];
    float b1 = row[64 + 2 * lane + 1];

    float ss = a0 * a0 + a1 * a1 + b0 * b0 + b1 * b1;
#pragma unroll
    for (int off = 16; off > 0; off >>= 1)
        ss += __shfl_xor_sync(0xFFFFFFFFu, ss, off);

    // 3.7982825 = sqrt(10 / ln 2): folds the exp2 scale into the data
    float rn = (1.0f / fmaxf(sqrtf(ss), 1e-12f)) * 3.7982825f;

    __half2 h0 = __floats2half2_rn(a0 * rn, a1 * rn);
    __half2 h1 = __floats2half2_rn(b0 * rn, b1 * rn);
    uint32_t* out = (uint32_t*)(g_xh + (size_t)(n0 + w) * F_DIM);
    out[lane]      = *(uint32_t*)&h0;   // features 2*lane, 2*lane+1
    out[32 + lane] = *(uint32_t*)&h1;   // features 64+2*lane, 64+2*lane+1
}

// ---------------------------------------------------------------------------
// Kernel 2: HMMA fp16 (f16 accumulate) 128x128x128 tile + fused exp2-sum.
// 16 warps, 32x32 warp tiles, XOR-swizzled smem (verbatim R12).
// ---------------------------------------------------------------------------
__global__ void __launch_bounds__(512, 2) simexp_kernel() {
    extern __shared__ char smem[];
    const uint32_t sbase = smem_u32(smem);
    const int tid  = threadIdx.x;
    const int wid  = tid >> 5;
    const int lane = tid & 31;

    // linear tile id -> (bi, bj), bj >= bi
    int t = blockIdx.x;
    int bi = (int)((129.0f - sqrtf(16641.0f - 8.0f * (float)t)) * 0.5f);
    while ((bi + 1) * (129 - (bi + 1)) / 2 <= t) ++bi;
    while (bi * (129 - bi) / 2 > t) --bi;
    const int bj = bi + (t - bi * (129 - bi) / 2);
    const bool diag = (bi == bj);

    // cooperative tile loads (2048 x 16B chunks over 512 threads)
    {
        const char* gA = (const char*)(g_xh + (size_t)bi * 128 * F_DIM);
#pragma unroll
        for (int it = 0; it < 4; ++it) {
            int idx = it * 512 + tid;
            int r = idx >> 4, q = idx & 15;
            CPA16(sbase + r * 256 + ((q ^ (r & 7)) << 4), gA + (size_t)idx * 16);
        }
        if (!diag) {
            const char* gB = (const char*)(g_xh + (size_t)bj * 128 * F_DIM);
#pragma unroll
            for (int it = 0; it < 4; ++it) {
                int idx = it * 512 + tid;
                int r = idx >> 4, q = idx & 15;
                CPA16(sbase + TILEB + r * 256 + ((q ^ (r & 7)) << 4), gB + (size_t)idx * 16);
            }
        }
        asm volatile("cp.async.commit_group;");
        asm volatile("cp.async.wait_group 0;" ::: "memory");
    }
    __syncthreads();

    const uint32_t aBase = sbase;
    const uint32_t bBase = diag ? sbase : (sbase + TILEB);

    const int wm = (wid >> 2) * 32;   // 4x4 warp grid
    const int wn = (wid & 3) * 32;
    const int g  = lane >> 3;
    const int lr = lane & 7;
    const int lrow = lane >> 2;
    const int lcol = (lane & 3) * 2;

    uint32_t acc[2][4][2];            // f16x2 packed accumulators
#pragma unroll
    for (int mt = 0; mt < 2; ++mt)
#pragma unroll
        for (int nt = 0; nt < 4; ++nt) {
            acc[mt][nt][0] = 0u;
            acc[mt][nt][1] = 0u;
        }

#pragma unroll
    for (int kc = 0; kc < 8; ++kc) {
        const int qa = kc * 2 + (g >> 1);
        const int qb = kc * 2 + (g & 1);
        uint32_t a[2][4];
#pragma unroll
        for (int mt = 0; mt < 2; ++mt) {
            int row = wm + mt * 16 + (g & 1) * 8 + lr;   // row & 7 == lr
            uint32_t addr = aBase + row * 256 + ((qa ^ lr) << 4);
            asm volatile("ldmatrix.sync.aligned.m8n8.x4.shared.b16 {%0,%1,%2,%3}, [%4];"
                         : "=r"(a[mt][0]), "=r"(a[mt][1]), "=r"(a[mt][2]), "=r"(a[mt][3])
                         : "r"(addr));
        }
        uint32_t bf[2][4];
#pragma unroll
        for (int np = 0; np < 2; ++np) {
            int row = wn + np * 16 + (g >> 1) * 8 + lr;  // row & 7 == lr
            uint32_t addr = bBase + row * 256 + ((qb ^ lr) << 4);
            asm volatile("ldmatrix.sync.aligned.m8n8.x4.shared.b16 {%0,%1,%2,%3}, [%4];"
                         : "=r"(bf[np][0]), "=r"(bf[np][1]), "=r"(bf[np][2]), "=r"(bf[np][3])
                         : "r"(addr));
        }
#pragma unroll
        for (int mt = 0; mt < 2; ++mt)
#pragma unroll
            for (int nt = 0; nt < 4; ++nt) {
                uint32_t b0 = bf[nt >> 1][(nt & 1) * 2];
                uint32_t b1 = bf[nt >> 1][(nt & 1) * 2 + 1];
                asm volatile(
                    "mma.sync.aligned.m16n8k16.row.col.f16.f16.f16.f16 "
                    "{%0,%1}, {%2,%3,%4,%5}, {%6,%7}, {%0,%1};"
                    : "+r"(acc[mt][nt][0]), "+r"(acc[mt][nt][1])
                    : "r"(a[mt][0]), "r"(a[mt][1]), "r"(a[mt][2]), "r"(a[mt][3]),
                      "r"(b0), "r"(b1));
            }
    }

    // epilogue: scale pre-folded -> bare 2^acc; skip i==j on diag tiles
    float s = 0.f;
#pragma unroll
    for (int mt = 0; mt < 2; ++mt)
#pragma unroll
        for (int nt = 0; nt < 4; ++nt)
#pragma unroll
            for (int h = 0; h < 2; ++h) {       // h=0: row lrow, h=1: row lrow+8
                int r_ = wm + mt * 16 + h * 8 + lrow;
                int c0 = wn + nt * 8 + lcol;
                float2 f = __half22float2(*(__half2*)&acc[mt][nt][h]);
                if (!diag || r_ != c0)     s += ex2a(f.x);
                if (!diag || r_ != c0 + 1) s += ex2a(f.y);
            }
    if (!diag) s *= 2.f;

    __shared__ float red[16];
#pragma unroll
    for (int off = 16; off > 0; off >>= 1)
        s += __shfl_down_sync(0xFFFFFFFFu, s, off);
    if (lane == 0) red[wid] = s;
    __syncthreads();
    if (tid == 0) {
        float tsum = 0.f;
#pragma unroll
        for (int w = 0; w < 16; ++w) tsum += red[w];
        g_part[blockIdx.x] = tsum;
    }
}

// ---------------------------------------------------------------------------
// Kernel 3: deterministic final reduction + log
// ---------------------------------------------------------------------------
__global__ void __launch_bounds__(256) finalize_kernel(float* __restrict__ out) {
    __shared__ float red[8];
    float s = 0.f;
    for (int i = threadIdx.x; i < NTILES; i += 256) s += g_part[i];
#pragma unroll
    for (int off = 16; off > 0; off >>= 1)
        s += __shfl_down_sync(0xFFFFFFFFu, s, off);
    if ((threadIdx.x & 31) == 0) red[threadIdx.x >> 5] = s;
    __syncthreads();
    if (threadIdx.x == 0) {
        float tsum = 0.f;
#pragma unroll
        for (int w = 0; w < 8; ++w) tsum += red[w];
        out[0] = logf(tsum);
    }
}

extern "C" void kernel_launch(void* const* d_in, const int* in_sizes, int n_in,
                              void* d_out, int out_size) {
    const float* x = (const float*)d_in[0];
    float* out = (float*)d_out;
    (void)in_sizes; (void)n_in; (void)out_size;

    cudaFuncSetAttribute(simexp_kernel, cudaFuncAttributeMaxDynamicSharedMemorySize, SM_TOTAL);

    normalize_kernel<<<N_TOT / 8, 256>>>(x);
    simexp_kernel<<<NTILES, 512, SM_TOTAL>>>();
    finalize_kernel<<<1, 256>>>(out);
}